// round 11
// baseline (speedup 1.0000x reference)
#include <cuda_runtime.h>
#include <cstdint>

// DCT_18769007084406 — persistent pipelined CTAs (cp.async.bulk ring + mbarrier),
// NBUF=3 -> 4 CTAs/SM. YCbCr mix in epilogue, butterfly DCT, closed-form affine.
// x[32,3,512,512] fp32 -> out[32,192,64,64] fp32

#define NT 256
#define GRID 608                      // 4 CTAs/SM x 152 SMs
#define PITCH 36                      // conflict-free both stages (R3-proven)
#define GF (24 * 8 * PITCH)           // 6912 floats
#define NBUF 3
#define CH_FLOATS 2048                // chunk = 1 channel x 8 rows x 256 cols
#define CH_BYTES 8192
#define BUF_FLOATS (NBUF * CH_FLOATS) // 6144
#define MBAR_F (BUF_FLOATS + GF + 2 * 192)     // float idx of mbars (byte%8==0)
#define SMEM_BYTES ((MBAR_F + 8) * 4)          // ~54 KB

static __device__ constexpr float B4[8][4] = {
  { 0.35355339059327373f,  0.35355339059327373f,  0.35355339059327373f,  0.35355339059327373f },
  { 0.49039264020161522f,  0.41573480615127262f,  0.27778511650980114f,  0.09754516100806417f },
  { 0.46193976625564337f,  0.19134171618254492f, -0.19134171618254492f, -0.46193976625564337f },
  { 0.41573480615127262f, -0.09754516100806417f, -0.49039264020161522f, -0.27778511650980114f },
  { 0.35355339059327373f, -0.35355339059327373f, -0.35355339059327373f,  0.35355339059327373f },
  { 0.27778511650980114f, -0.49039264020161522f,  0.09754516100806417f,  0.41573480615127262f },
  { 0.19134171618254492f, -0.46193976625564337f,  0.46193976625564337f, -0.19134171618254492f },
  { 0.09754516100806417f, -0.27778511650980114f,  0.41573480615127262f, -0.49039264020161522f }
};

__device__ __forceinline__ void mbar_wait(uint32_t addr, uint32_t parity) {
    asm volatile(
        "{\n\t"
        ".reg .pred P;\n\t"
        "W_%=:\n\t"
        "mbarrier.try_wait.parity.acquire.cta.shared::cta.b64 P, [%0], %1, 0x989680;\n\t"
        "@P bra.uni D_%=;\n\t"
        "bra.uni W_%=;\n\t"
        "D_%=:\n\t"
        "}"
        :: "r"(addr), "r"(parity) : "memory");
}

// Issue one 8 KB chunk (chunk index n -> strip, channel) into ring slot n%3.
__device__ __forceinline__ void issue_chunk(const float* __restrict__ x,
                                            int cta, int n,
                                            uint32_t buf_s, uint32_t mbar_s)
{
    const int ks = n / 3;             // strip ordinal for this CTA
    const int c  = n - ks * 3;        // channel
    const int s  = cta + ks * GRID;
    const int b = s >> 7, rh = s & 127, r = rh >> 1, half = rh & 1;
    const float* src = x + (size_t)(b * 3 + c) * 262144 + r * 8 * 512 + half * 256;
    const int slot = n % 3;
    const uint32_t dst = buf_s + (uint32_t)slot * CH_BYTES;
    const uint32_t bar = mbar_s + (uint32_t)slot * 8;

    asm volatile("mbarrier.arrive.expect_tx.shared.b64 _, [%0], %1;"
                 :: "r"(bar), "r"((uint32_t)CH_BYTES) : "memory");
    #pragma unroll
    for (int i = 0; i < 8; ++i)
        asm volatile("cp.async.bulk.shared::cluster.global.mbarrier::complete_tx::bytes "
                     "[%0], [%1], %2, [%3];"
                     :: "r"(dst + i * 1024), "l"(src + i * 512),
                        "r"(1024), "r"(bar) : "memory");
}

__global__ void __launch_bounds__(NT)
dct_fused_kernel(const float* __restrict__ x,
                 const float* __restrict__ max_,
                 const float* __restrict__ min_,
                 const float* __restrict__ ycw,
                 float* __restrict__ out)
{
    extern __shared__ float sm[];
    float*  BUF = sm;                 // [3][2048]
    float*  G   = sm + BUF_FLOATS;    // [(c*64 + u*8 + j)*PITCH + bw]
    float2* aff = (float2*)(sm + BUF_FLOATS + GF);

    const uint32_t buf_s  = (uint32_t)__cvta_generic_to_shared(BUF);
    const uint32_t mbar_s = (uint32_t)__cvta_generic_to_shared(sm + MBAR_F);

    const int t   = threadIdx.x;
    const int cta = blockIdx.x;

    if (t == 0) {
        #pragma unroll
        for (int i = 0; i < NBUF; ++i)
            asm volatile("mbarrier.init.shared.b64 [%0], 1;"
                         :: "r"(mbar_s + i * 8) : "memory");
    }
    __syncthreads();

    const int nstrips = cta < 4096 ? (4095 - cta) / GRID + 1 : 0;
    const int nchunks = 3 * nstrips;

    if (t == 0 && nchunks > 0) {
        const int pro = nchunks < NBUF ? nchunks : NBUF;
        for (int n = 0; n < pro; ++n)
            issue_chunk(x, cta, n, buf_s, mbar_s);
    }

    const int j   = t & 7;
    const int bw  = t >> 3;           // 0..31
    const int bwB = t & 31;
    const int u   = t >> 5;           // 0..7

    int n = 0;
    for (int k = 0; k < nstrips; ++k) {
        const int s = cta + k * GRID;
        const int b = s >> 7, rh = s & 127, r = rh >> 1, half = rh & 1;

        float mx = 0.f, mn = 0.f;
        if (t < 192) { mx = max_[b * 192 + t]; mn = min_[b * 192 + t]; }

        // ---- Stage A: 3 chunks -> vertical DCT into G --------------------
        #pragma unroll
        for (int c = 0; c < 3; ++c, ++n) {
            const int slot = n % 3;
            mbar_wait(mbar_s + slot * 8, (n / 3) & 1);

            const float* IN = BUF + slot * CH_FLOATS;
            float v[8];
            #pragma unroll
            for (int i = 0; i < 8; ++i)
                v[i] = IN[i * 256 + t];

            const float s0 = v[0] + v[7], s1 = v[1] + v[6], s2 = v[2] + v[5], s3 = v[3] + v[4];
            const float d0 = v[0] - v[7], d1 = v[1] - v[6], d2 = v[2] - v[5], d3 = v[3] - v[4];

            float* Gc = G + (c * 64 + j) * PITCH + bw;
            #pragma unroll
            for (int uu = 0; uu < 8; uu += 2) {
                float e = B4[uu][0] * s0;
                e = fmaf(B4[uu][1], s1, e);
                e = fmaf(B4[uu][2], s2, e);
                e = fmaf(B4[uu][3], s3, e);
                Gc[uu * 8 * PITCH] = e;
                float o = B4[uu + 1][0] * d0;
                o = fmaf(B4[uu + 1][1], d1, o);
                o = fmaf(B4[uu + 1][2], d2, o);
                o = fmaf(B4[uu + 1][3], d3, o);
                Gc[(uu + 1) * 8 * PITCH] = o;
            }

            __syncthreads();          // slot consumed by all threads
            if (t == 0 && n + NBUF < nchunks)
                issue_chunk(x, cta, n + NBUF, buf_s, mbar_s);
        }

        if (t < 192) {
            const float d  = mx - mn + 1e-6f;
            const float rr = 1.0f / d;
            float r2 = rr * rr, r4 = r2 * r2, r8 = r4 * r4, r16 = r8 * r8;
            const float r32 = r16 * r16;
            aff[t] = make_float2(r32, -mn * (rr * (1.0f - r32) / (1.0f - rr)));
        }
        __syncthreads();

        // ---- Stage B: channel mix + horizontal DCT + affine + store ------
        const size_t outb = (size_t)b * 192 * 4096 + (size_t)r * 64 + half * 32 + bwB;

        #pragma unroll
        for (int q = 0; q < 3; ++q) {
            float m[8];
            #pragma unroll
            for (int c = 0; c < 3; ++c) {
                const float w = ycw[q * 3 + c];
                #pragma unroll
                for (int jj = 0; jj < 8; ++jj) {
                    const float g = G[((c * 8 + u) * 8 + jj) * PITCH + bwB];
                    m[jj] = (c == 0) ? w * g : fmaf(w, g, m[jj]);
                }
            }

            const float s0 = m[0] + m[7], s1 = m[1] + m[6], s2 = m[2] + m[5], s3 = m[3] + m[4];
            const float d0 = m[0] - m[7], d1 = m[1] - m[6], d2 = m[2] - m[5], d3 = m[3] - m[4];

            const int kbase = q * 64 + u * 8;
            #pragma unroll
            for (int vv = 0; vv < 8; vv += 2) {
                float e = B4[vv][0] * s0;
                e = fmaf(B4[vv][1], s1, e);
                e = fmaf(B4[vv][2], s2, e);
                e = fmaf(B4[vv][3], s3, e);
                float2 sb = aff[kbase + vv];
                out[outb + (size_t)(kbase + vv) * 4096] = fmaf(e, sb.x, sb.y);

                float o = B4[vv + 1][0] * d0;
                o = fmaf(B4[vv + 1][1], d1, o);
                o = fmaf(B4[vv + 1][2], d2, o);
                o = fmaf(B4[vv + 1][3], d3, o);
                sb = aff[kbase + vv + 1];
                out[outb + (size_t)(kbase + vv + 1) * 4096] = fmaf(o, sb.x, sb.y);
            }
        }
        __syncthreads();              // G + aff free for next strip
    }
}

extern "C" void kernel_launch(void* const* d_in, const int* in_sizes, int n_in,
                              void* d_out, int out_size)
{
    const float* x    = (const float*)d_in[0];
    const float* max_ = (const float*)d_in[1];
    const float* min_ = (const float*)d_in[2];
    const float* ycw  = (const float*)d_in[3];
    float* out = (float*)d_out;

    cudaFuncSetAttribute(dct_fused_kernel,
                         cudaFuncAttributeMaxDynamicSharedMemorySize, SMEM_BYTES);

    dct_fused_kernel<<<GRID, NT, SMEM_BYTES>>>(x, max_, min_, ycw, out);
}